// round 14
// baseline (speedup 1.0000x reference)
#include <cuda_runtime.h>
#include <cuda_fp16.h>
#include <math.h>
#include <stdint.h>

#define NE 8
#define DM 1024
#define NBz 4
#define NSz 2048
#define NT 8192           // tokens
#define NP 16384          // (token,slot) pairs
#define NROWT 64          // max row-tiles per expert (8192/128)

// ---------------- device scratch (no allocation allowed) -------------------
__device__ __align__(1024) __half g_xh[(size_t)NT * DM];
__device__ __align__(1024) __half g_w1h[(size_t)NE * DM * DM];   // natural [e][k][n]
__device__ __align__(1024) __half g_w2h[(size_t)NE * DM * DM];
__device__ __align__(1024) __half g_hh[(size_t)NP * DM];
__device__ int   g_order[NP];
__device__ float g_wt[NP];
__device__ int   g_eid[NP];
__device__ int   g_count[NE], g_off[NE], g_pos[NE];
__device__ int   g_toff[NE + 1];
__device__ int   g_done1[NE * NROWT];
__device__ int   g_convdone;
__device__ float g_zsum, g_proxy[NBz * NE], g_dens[NBz * NE];

// ---------------- helpers ---------------------------------------------------
__device__ __forceinline__ uint32_t smem_u32(const void* p) {
    uint32_t a;
    asm("{ .reg .u64 t; cvta.to.shared.u64 t, %1; cvt.u32.u64 %0, t; }" : "=r"(a) : "l"(p));
    return a;
}
__device__ __forceinline__ void cp16(uint32_t dst, const void* src) {
    asm volatile("cp.async.cg.shared.global [%0], [%1], 16;" :: "r"(dst), "l"(src));
}
__device__ __forceinline__ void cp_commit() { asm volatile("cp.async.commit_group;" ::: "memory"); }
__device__ __forceinline__ void cp_wait1() { asm volatile("cp.async.wait_group 1;" ::: "memory"); }
__device__ __forceinline__ void cp_wait0() { asm volatile("cp.async.wait_group 0;" ::: "memory"); }

__device__ __forceinline__ void ldmat4(uint32_t* r, uint32_t addr) {
    asm volatile("ldmatrix.sync.aligned.m8n8.x4.shared.b16 {%0,%1,%2,%3}, [%4];"
                 : "=r"(r[0]), "=r"(r[1]), "=r"(r[2]), "=r"(r[3]) : "r"(addr));
}
__device__ __forceinline__ void ldmat2t(uint32_t* r, uint32_t addr) {
    asm volatile("ldmatrix.sync.aligned.m8n8.x2.trans.shared.b16 {%0,%1}, [%2];"
                 : "=r"(r[0]), "=r"(r[1]) : "r"(addr));
}
__device__ __forceinline__ void mma_f16(float* c, const uint32_t* a, const uint32_t* b) {
    asm volatile("mma.sync.aligned.m16n8k16.row.col.f32.f16.f16.f32 "
                 "{%0,%1,%2,%3}, {%4,%5,%6,%7}, {%8,%9}, {%0,%1,%2,%3};"
                 : "+f"(c[0]), "+f"(c[1]), "+f"(c[2]), "+f"(c[3])
                 : "r"(a[0]), "r"(a[1]), "r"(a[2]), "r"(a[3]), "r"(b[0]), "r"(b[1]));
}
__device__ __forceinline__ float gelu_exact(float v) {
    return 0.5f * v * (1.0f + erff(v * 0.70710678118654752f));
}
__device__ __forceinline__ void cvt4(const float* src, __half2* dst, size_t i) {
    float4 v = ((const float4*)src)[i];
    dst[2 * i]     = __half2(__float2half_rn(v.x), __float2half_rn(v.y));
    dst[2 * i + 1] = __half2(__float2half_rn(v.z), __float2half_rn(v.w));
}

// ---------------- init / gating / scatter ----------------------------------
__global__ void init_kernel() {
    int t = threadIdx.x;   // 512 threads
    if (t < NE) { g_count[t] = 0; g_pos[t] = 0; }
    if (t == 0) { g_zsum = 0.0f; g_convdone = 0; }
    if (t < NBz * NE) { g_proxy[t] = 0.0f; g_dens[t] = 0.0f; }
    if (t < NE * NROWT) g_done1[t] = 0;
}

// gating + fp16(x) + fp16(W1) conversion + zero(out)
__global__ __launch_bounds__(256) void gate_kernel(
    const float* __restrict__ x, const float* __restrict__ Wg,
    const float* __restrict__ W1, float* __restrict__ out) {
    __shared__ float xs[DM];
    __shared__ float logits[NE];
    int t = blockIdx.x;
    const float* xr = x + (size_t)t * DM;
    for (int i = threadIdx.x; i < DM; i += blockDim.x) xs[i] = xr[i];
    __syncthreads();
    for (int i = threadIdx.x; i < DM / 2; i += blockDim.x) {
        __half2 v = __half2(__float2half_rn(xs[2 * i]), __float2half_rn(xs[2 * i + 1]));
        ((__half2*)(g_xh + (size_t)t * DM))[i] = v;
    }
    int w = threadIdx.x >> 5, lane = threadIdx.x & 31;
    const float* wg = Wg + w * DM;
    float s = 0.0f;
    for (int k = lane; k < DM; k += 32) s += xs[k] * wg[k];
#pragma unroll
    for (int o = 16; o; o >>= 1) s += __shfl_xor_sync(0xffffffffu, s, o);
    if (lane == 0) logits[w] = s;
    __syncthreads();
    if (threadIdx.x == 0) {
        float m = -1e30f;
#pragma unroll
        for (int e = 0; e < NE; e++) m = fmaxf(m, logits[e]);
        float p[NE], sum = 0.0f;
#pragma unroll
        for (int e = 0; e < NE; e++) { p[e] = expf(logits[e] - m); sum += p[e]; }
        float inv_sum = 1.0f / sum;
        float z = m + logf(sum);
        atomicAdd(&g_zsum, z * z);
        int b = t / NSz;
#pragma unroll
        for (int e = 0; e < NE; e++) atomicAdd(&g_proxy[b * NE + e], p[e] * inv_sum);
        int i0 = 0;
#pragma unroll
        for (int e = 1; e < NE; e++) if (p[e] > p[i0]) i0 = e;
        int i1 = (i0 == 0) ? 1 : 0;
#pragma unroll
        for (int e = 0; e < NE; e++) if (e != i0 && p[e] > p[i1]) i1 = e;
        atomicAdd(&g_dens[b * NE + i0], 1.0f);
        float v0 = p[i0], v1 = p[i1];
        float invw = 1.0f / (v0 + v1);
        g_wt[2 * t] = v0 * invw;
        g_wt[2 * t + 1] = v1 * invw;
        g_eid[2 * t] = i0;
        g_eid[2 * t + 1] = i1;
        atomicAdd(&g_count[i0], 1);
        atomicAdd(&g_count[i1], 1);
    }
    // extra grid-wide work: one float4 of W1 and one float4 of out per thread
    size_t gi = (size_t)blockIdx.x * blockDim.x + threadIdx.x;
    cvt4(W1, (__half2*)g_w1h, gi);                      // NE*DM*DM/4 == NT*256 exactly
    ((float4*)out)[gi] = make_float4(0.f, 0.f, 0.f, 0.f);   // NT*DM/4 == NT*256 exactly
}

__global__ void scan_kernel() {
    if (threadIdx.x == 0) {
        int acc = 0, tacc = 0;
#pragma unroll
        for (int e = 0; e < NE; e++) {
            g_off[e] = acc;
            g_toff[e] = tacc;
            acc += g_count[e];
            tacc += ((g_count[e] + 127) >> 7) * 8;   // rowtiles * n-tiles
        }
        g_toff[NE] = tacc;
    }
}

__global__ void scatter_kernel() {
    int p = blockIdx.x * blockDim.x + threadIdx.x;
    if (p >= NP) return;
    int e = g_eid[p];
    int idx = atomicAdd(&g_pos[e], 1);
    g_order[g_off[e] + idx] = p;
}

// ---------------- fused HMMA GEMM1 + W2-convert + GEMM2 --------------------
// CTA tile 128x128, K chunk 64, 8 warps (2x4), warp tile 64x32, 3-stage cp.async
#define BM 128
#define BN 128
#define BK 64
#define NCHUNK (DM / BK)                 // 16
#define ASTRIDE 144                      // 128B data + 16B pad
#define BSTRIDE 272                      // 256B data + 16B pad
#define A_BYTES (BM * ASTRIDE)           // 18432
#define B_BYTES (BK * BSTRIDE)           // 17408
#define STAGE_BYTES (A_BYTES + B_BYTES)  // 35840
#define A_OFF(s) ((s) * STAGE_BYTES)
#define B_OFF(s) ((s) * STAGE_BYTES + A_BYTES)
#define TOKS_OFF (3 * STAGE_BYTES)       // 107520
#define PV_OFF   (TOKS_OFF + 512)
#define WV_OFF   (PV_OFF + 512)
#define SMEM_TOTAL (WV_OFF + 512)        // 109056
#define NGEMM_CTAS 296

__global__ __launch_bounds__(256, 2) void moe_fused(
    const float* __restrict__ b1, const float* __restrict__ b2,
    const float* __restrict__ W2src, float* __restrict__ outp) {
    extern __shared__ char smem[];
    uint32_t sb = smem_u32(smem);
    int tid = threadIdx.x;
    int wid = tid >> 5, lane = tid & 31;
    int wr = wid >> 2, wc = wid & 3;      // 2 x 4 warp grid
    int m0w = wr * 64, n0w = wc * 32;

    int* toks = (int*)(smem + TOKS_OFF);
    int T1 = g_toff[NE];
    int total = 2 * T1 + NGEMM_CTAS;

    for (int t = blockIdx.x; t < total; t += NGEMM_CTAS) {
        // -------- W2 conversion slice --------
        if (t >= T1 && t < T1 + NGEMM_CTAS) {
            int ci = t - T1;
            const size_t totalf4 = (size_t)NE * DM * DM / 4;
            size_t per = (totalf4 + NGEMM_CTAS - 1) / NGEMM_CTAS;
            size_t lo = (size_t)ci * per;
            size_t hi = lo + per; if (hi > totalf4) hi = totalf4;
            for (size_t i = lo + tid; i < hi; i += 256)
                cvt4(W2src, (__half2*)g_w2h, i);
            __threadfence();
            __syncthreads();
            if (tid == 0) atomicAdd(&g_convdone, 1);
            continue;
        }
        int phase2 = (t >= T1) ? 1 : 0;
        int tt = phase2 ? (t - T1 - NGEMM_CTAS) : t;

        // decode tile -> (expert, row tile, n tile)
        int e = 0;
#pragma unroll
        for (int k = 1; k < NE; k++) if (tt >= g_toff[k]) e = k;
        int tl = tt - g_toff[e];
        int rowtile = tl >> 3;
        int row0 = rowtile * BM;
        int n0 = (tl & 7) * BN;
        int cnt = g_count[e];
        int base = g_off[e];

        // -------- dependency wait (gemm2 only) --------
        if (phase2) {
            if (tid == 0) {
                while (atomicAdd(&g_done1[e * NROWT + rowtile], 0) < 8) { }
                while (atomicAdd(&g_convdone, 0) < NGEMM_CTAS) { }
                __threadfence();
            }
        }
        __syncthreads();   // also fences previous tile's epilogue smem reads
        if (tid < BM) {
            int r = row0 + tid;
            if (!phase2) {
                toks[tid] = (r < cnt) ? (g_order[base + r] >> 1) : 0;
            } else {
                toks[tid] = (r < cnt) ? (base + r) : 0;
                int p = (r < cnt) ? g_order[base + r] : 0;
                ((int*)(smem + PV_OFF))[tid] = p;
                ((float*)(smem + WV_OFF))[tid] = g_wt[p];
            }
        }
        __syncthreads();

        const __half* Ah = phase2 ? g_hh : g_xh;
        const __half* Wh = (phase2 ? g_w2h : g_w1h) + (size_t)e * DM * DM;
        const float* bias = phase2 ? b2 : b1;

        float acc[4][4][4];
#pragma unroll
        for (int i = 0; i < 4; i++)
#pragma unroll
            for (int j = 0; j < 4; j++)
#pragma unroll
                for (int q = 0; q < 4; q++) acc[i][j][q] = 0.0f;

        auto load_chunk = [&](int c, int s) {
            int k0 = c * BK;
#pragma unroll
            for (int it = 0; it < 4; it++) {
                int i = tid + it * 256;
                int r = i >> 3, cq = i & 7;
                cp16(sb + A_OFF(s) + r * ASTRIDE + cq * 16,
                     Ah + (size_t)toks[r] * DM + k0 + cq * 8);
            }
#pragma unroll
            for (int it = 0; it < 4; it++) {
                int i = tid + it * 256;
                int k = i >> 4, cq = i & 15;
                cp16(sb + B_OFF(s) + k * BSTRIDE + cq * 16,
                     Wh + (size_t)(k0 + k) * DM + n0 + cq * 8);
            }
            cp_commit();
        };

        auto compute = [&](int s) {
#pragma unroll
            for (int kk = 0; kk < 4; kk++) {
                int kb = kk * 16;
                uint32_t a[4][4], b[4][2];
                int arow = m0w + (lane & 15);
                int acolb = (kb + ((lane & 16) ? 8 : 0)) * 2;
#pragma unroll
                for (int i = 0; i < 4; i++)
                    ldmat4(a[i], sb + A_OFF(s) + (arow + i * 16) * ASTRIDE + acolb);
                int brow = kb + (lane & 15);
#pragma unroll
                for (int j = 0; j < 4; j++)
                    ldmat2t(b[j], sb + B_OFF(s) + brow * BSTRIDE + (n0w + j * 8) * 2);
#pragma unroll
                for (int i = 0; i < 4; i++)
#pragma unroll
                    for (int j = 0; j < 4; j++) mma_f16(acc[i][j], a[i], b[j]);
            }
        };

        load_chunk(0, 0);
        load_chunk(1, 1);
        for (int c = 0; c < NCHUNK; c++) {
            int s = c % 3;
            if (c < NCHUNK - 1) cp_wait1(); else cp_wait0();
            __syncthreads();
            if (c + 2 < NCHUNK) load_chunk(c + 2, (c + 2) % 3);
            compute(s);
        }

        // ---------------- epilogue ----------------
#pragma unroll
        for (int i = 0; i < 4; i++) {
            int rb = m0w + i * 16 + (lane >> 2);
#pragma unroll
            for (int j = 0; j < 4; j++) {
                int gcol = n0 + n0w + j * 8 + (lane & 3) * 2;
                float bv0 = bias[e * DM + gcol];
                float bv1 = bias[e * DM + gcol + 1];
#pragma unroll
                for (int h = 0; h < 2; h++) {
                    int r = rb + h * 8;
                    if (row0 + r >= cnt) continue;
                    float v0 = acc[i][j][2 * h]     + bv0;
                    float v1 = acc[i][j][2 * h + 1] + bv1;
                    if (!phase2) {
                        float gg0 = gelu_exact(v0), gg1 = gelu_exact(v1);
                        __half2 hv = __half2(__float2half_rn(gg0), __float2half_rn(gg1));
                        size_t o = (size_t)(base + row0 + r) * DM + gcol;
                        *(__half2*)(g_hh + o) = hv;
                    } else {
                        float wv = ((float*)(smem + WV_OFF))[r];
                        int p = ((int*)(smem + PV_OFF))[r];
                        size_t o = (size_t)(p >> 1) * DM + gcol;
                        atomicAdd(&outp[o],     v0 * wv);
                        atomicAdd(&outp[o + 1], v1 * wv);
                    }
                }
            }
        }

        // -------- publish (gemm1 only) --------
        if (!phase2) {
            __threadfence();
            __syncthreads();
            if (tid == 0) atomicAdd(&g_done1[e * NROWT + rowtile], 1);
        }
    }
}

// ---------------- losses -----------------------------------------------------
__global__ void finalize_kernel(float* __restrict__ out) {
    if (threadIdx.x == 0) {
        float zloss = g_zsum / (float)NT;
        float bal = 0.0f;
#pragma unroll
        for (int i = 0; i < NBz * NE; i++)
            bal += (g_proxy[i] / (float)NSz) * (g_dens[i] / (float)NSz);
        bal = bal / (float)(NBz * NE) * (float)(NE * NE);
        out[(size_t)NT * DM]     = bal * 0.01f + zloss * 0.001f;
        out[(size_t)NT * DM + 1] = bal;
    }
}

// ---------------- launch ----------------------------------------------------
extern "C" void kernel_launch(void* const* d_in, const int* in_sizes, int n_in,
                              void* d_out, int out_size) {
    const float* x  = (const float*)d_in[0];
    const float* Wg = (const float*)d_in[1];
    const float* W1 = (const float*)d_in[2];
    const float* b1 = (const float*)d_in[3];
    const float* W2 = (const float*)d_in[4];
    const float* b2 = (const float*)d_in[5];
    float* out = (float*)d_out;

    cudaFuncSetAttribute(moe_fused, cudaFuncAttributeMaxDynamicSharedMemorySize, SMEM_TOTAL);

    init_kernel<<<1, 512>>>();
    gate_kernel<<<NT, 256>>>(x, Wg, W1, out);
    scan_kernel<<<1, 32>>>();
    scatter_kernel<<<NP / 256, 256>>>();

    moe_fused<<<NGEMM_CTAS, 256, SMEM_TOTAL>>>(b1, b2, W2, out);
    finalize_kernel<<<1, 32>>>(out);
}